// round 1
// baseline (speedup 1.0000x reference)
#include <cuda_runtime.h>
#include <cuda_fp16.h>
#include <cstdint>

// Problem constants
#define NROWS 65536
#define DD    512
#define NL    8
#define HH    256
#define HALFD 256

// Tiling
#define MT      64      // rows per CTA
#define THREADS 512     // 16 warps: 2 (M) x 8 (N)
#define LDE     264     // half-elem leading dim for e/h tiles (pad 8 halves: conflict-free)
#define LDO     260     // float leading dim for o/s tiles

// Packed fp16 weights in mma-B-fragment order:
// [layer][mat(4: Ws1,Ws2,Wt1,Wt2)][kstep 16][ntile 32][lane 32] as uint2 {b0b1, b2b3}
__device__ uint2 g_wpack[NL * 4 * 16 * 32 * 32];

__global__ void pack_w(const float* __restrict__ Ws1, const float* __restrict__ Ws2,
                       const float* __restrict__ Wt1, const float* __restrict__ Wt2)
{
    int idx = blockIdx.x * blockDim.x + threadIdx.x;
    if (idx >= NL * 4 * 16 * 32 * 32) return;
    int lane  = idx & 31;
    int nt    = (idx >> 5) & 31;
    int ks    = (idx >> 10) & 15;
    int mat   = (idx >> 14) & 3;
    int layer = idx >> 16;
    const float* W = (mat == 0) ? Ws1 : (mat == 1) ? Ws2 : (mat == 2) ? Wt1 : Wt2;
    W += (size_t)layer * HH * HALFD;   // every matrix is 256x256 [K][N] row-major
    int n  = nt * 8 + (lane >> 2);
    int k0 = ks * 16 + (lane & 3) * 2;
    __half2 p0 = __floats2half2_rn(W[k0 * 256 + n],       W[(k0 + 1) * 256 + n]);
    __half2 p1 = __floats2half2_rn(W[(k0 + 8) * 256 + n], W[(k0 + 9) * 256 + n]);
    uint2 v;
    v.x = *reinterpret_cast<uint32_t*>(&p0);
    v.y = *reinterpret_cast<uint32_t*>(&p1);
    g_wpack[idx] = v;
}

__device__ __forceinline__ void mma16816(float c[4], const uint32_t a[4], uint32_t b0, uint32_t b1)
{
    asm volatile(
        "mma.sync.aligned.m16n8k16.row.col.f32.f16.f16.f32 "
        "{%0,%1,%2,%3},{%4,%5,%6,%7},{%8,%9},{%0,%1,%2,%3};\n"
        : "+f"(c[0]), "+f"(c[1]), "+f"(c[2]), "+f"(c[3])
        : "r"(a[0]), "r"(a[1]), "r"(a[2]), "r"(a[3]), "r"(b0), "r"(b1));
}

__device__ __forceinline__ void ldmA(uint32_t a[4], uint32_t addr)
{
    asm volatile(
        "ldmatrix.sync.aligned.m8n8.x4.shared.b16 {%0,%1,%2,%3},[%4];\n"
        : "=r"(a[0]), "=r"(a[1]), "=r"(a[2]), "=r"(a[3])
        : "r"(addr));
}

// C = A(64x256, f16 smem, LDE) @ W(256x256 packed) ; warp tile 32x32
__device__ __forceinline__ void gemm_tile(uint32_t aBase, const uint2* __restrict__ wp,
                                          float acc[2][4][4],
                                          int lane, int wm, int wn, int rowoff, int koff)
{
    #pragma unroll
    for (int mt = 0; mt < 2; mt++)
        #pragma unroll
        for (int nt = 0; nt < 4; nt++)
            #pragma unroll
            for (int q = 0; q < 4; q++) acc[mt][nt][q] = 0.f;

    const uint32_t a0 = aBase + (uint32_t)((wm * 32 + rowoff) * LDE + koff) * 2;

    uint2 b[4];
    #pragma unroll
    for (int nt = 0; nt < 4; nt++) b[nt] = wp[(wn * 4 + nt) * 32 + lane];

    #pragma unroll
    for (int ks = 0; ks < 16; ks++) {
        uint32_t a[2][4];
        #pragma unroll
        for (int mt = 0; mt < 2; mt++)
            ldmA(a[mt], a0 + mt * (16 * LDE * 2) + ks * 32);

        uint2 bn[4];
        if (ks < 15) {
            #pragma unroll
            for (int nt = 0; nt < 4; nt++)
                bn[nt] = wp[((ks + 1) * 32 + wn * 4 + nt) * 32 + lane];
        }

        #pragma unroll
        for (int mt = 0; mt < 2; mt++)
            #pragma unroll
            for (int nt = 0; nt < 4; nt++)
                mma16816(acc[mt][nt], a[mt], b[nt].x, b[nt].y);

        if (ks < 15) {
            #pragma unroll
            for (int nt = 0; nt < 4; nt++) b[nt] = bn[nt];
        }
    }
}

__device__ __forceinline__ float tanh_acc(float x)
{
    x = fminf(fmaxf(x, -15.f), 15.f);
    float e2 = __expf(2.f * x);
    return __fdividef(e2 - 1.f, e2 + 1.f);
}

// SMEM layout (bytes)
#define SM_E   0
#define SM_H   (MT * LDE * 2)                 // 33792
#define SM_O   (SM_H + MT * LDE * 2)          // 67584
#define SM_S   (SM_O + MT * LDO * 4)          // 134144
#define SM_LJ  (SM_S + MT * LDO * 4)          // 200704
#define SM_TOT (SM_LJ + MT * 8 * 4)           // 202752

__global__ void __launch_bounds__(THREADS, 1) nvp_main(
    const float* __restrict__ z,
    const float* __restrict__ bs1, const float* __restrict__ bs2,
    const float* __restrict__ bt1, const float* __restrict__ bt2,
    float* __restrict__ out)
{
    extern __shared__ char smraw[];
    __half* e_s  = reinterpret_cast<__half*>(smraw + SM_E);
    __half* h_s  = reinterpret_cast<__half*>(smraw + SM_H);
    float*  o_s  = reinterpret_cast<float*>(smraw + SM_O);
    float*  s_s  = reinterpret_cast<float*>(smraw + SM_S);
    float*  lj_s = reinterpret_cast<float*>(smraw + SM_LJ);

    const int tid  = threadIdx.x;
    const int row0 = blockIdx.x * MT;

    // Load: z row -> (e f16 smem, o f32 smem); even half of output is the identity copy.
    for (int idx = tid; idx < MT * 256; idx += THREADS) {
        int r = idx >> 8, c = idx & 255;
        float2 p = reinterpret_cast<const float2*>(z + (size_t)(row0 + r) * DD)[c];
        e_s[r * LDE + c] = __float2half_rn(p.x);
        o_s[r * LDO + c] = p.y;
        out[(size_t)(row0 + r) * DD + c] = p.x;
    }
    __syncthreads();

    const int warp = tid >> 5, lane = tid & 31;
    const int wm = warp & 1, wn = warp >> 1;      // 2 x 8 warp grid
    const int g = lane >> 2, tg = lane & 3;
    const int mat = lane >> 3, within = lane & 7;
    const int rowoff = ((mat & 1) << 3) + within; // ldmatrix per-lane row
    const int koff   = (mat >> 1) << 3;
    const uint32_t aE = (uint32_t)__cvta_generic_to_shared(e_s);
    const uint32_t aH = (uint32_t)__cvta_generic_to_shared(h_s);

    float lj[4] = {0.f, 0.f, 0.f, 0.f};
    float acc[2][4][4];

    for (int layer = 0; layer < NL; layer++) {
        const uint2* wl = g_wpack + (size_t)(layer * 4) * 16384;

        // ---------- s-MLP: h = relu(e @ Ws1 + bs1) ----------
        gemm_tile(aE, wl, acc, lane, wm, wn, rowoff, koff);
        __syncthreads();   // previous readers of h_s are done
        #pragma unroll
        for (int mt = 0; mt < 2; mt++)
            #pragma unroll
            for (int nt = 0; nt < 4; nt++) {
                int col0 = wn * 32 + nt * 8 + tg * 2;
                float2 bb = *reinterpret_cast<const float2*>(bs1 + layer * HH + col0);
                int r0 = wm * 32 + mt * 16 + g;
                __half2 v0 = __floats2half2_rn(fmaxf(acc[mt][nt][0] + bb.x, 0.f),
                                               fmaxf(acc[mt][nt][1] + bb.y, 0.f));
                __half2 v1 = __floats2half2_rn(fmaxf(acc[mt][nt][2] + bb.x, 0.f),
                                               fmaxf(acc[mt][nt][3] + bb.y, 0.f));
                *reinterpret_cast<__half2*>(h_s + r0 * LDE + col0)       = v0;
                *reinterpret_cast<__half2*>(h_s + (r0 + 8) * LDE + col0) = v1;
            }
        __syncthreads();

        // ---------- s = tanh(h @ Ws2 + bs2) ----------
        gemm_tile(aH, wl + 16384, acc, lane, wm, wn, rowoff, koff);
        #pragma unroll
        for (int mt = 0; mt < 2; mt++)
            #pragma unroll
            for (int nt = 0; nt < 4; nt++) {
                int col0 = wn * 32 + nt * 8 + tg * 2;
                float2 bb = *reinterpret_cast<const float2*>(bs2 + layer * HALFD + col0);
                int r0 = wm * 32 + mt * 16 + g;
                float s0 = tanh_acc(acc[mt][nt][0] + bb.x);
                float s1 = tanh_acc(acc[mt][nt][1] + bb.y);
                float s2 = tanh_acc(acc[mt][nt][2] + bb.x);
                float s3 = tanh_acc(acc[mt][nt][3] + bb.y);
                *reinterpret_cast<float2*>(s_s + r0 * LDO + col0)       = make_float2(s0, s1);
                *reinterpret_cast<float2*>(s_s + (r0 + 8) * LDO + col0) = make_float2(s2, s3);
                lj[mt * 2]     += s0 + s1;
                lj[mt * 2 + 1] += s2 + s3;
            }
        __syncthreads();  // all warps done reading h_s (s-GEMM2)

        // ---------- t-MLP: h = relu(e @ Wt1 + bt1) ----------
        gemm_tile(aE, wl + 2 * 16384, acc, lane, wm, wn, rowoff, koff);
        #pragma unroll
        for (int mt = 0; mt < 2; mt++)
            #pragma unroll
            for (int nt = 0; nt < 4; nt++) {
                int col0 = wn * 32 + nt * 8 + tg * 2;
                float2 bb = *reinterpret_cast<const float2*>(bt1 + layer * HH + col0);
                int r0 = wm * 32 + mt * 16 + g;
                __half2 v0 = __floats2half2_rn(fmaxf(acc[mt][nt][0] + bb.x, 0.f),
                                               fmaxf(acc[mt][nt][1] + bb.y, 0.f));
                __half2 v1 = __floats2half2_rn(fmaxf(acc[mt][nt][2] + bb.x, 0.f),
                                               fmaxf(acc[mt][nt][3] + bb.y, 0.f));
                *reinterpret_cast<__half2*>(h_s + r0 * LDE + col0)       = v0;
                *reinterpret_cast<__half2*>(h_s + (r0 + 8) * LDE + col0) = v1;
            }
        __syncthreads();

        // ---------- t = h @ Wt2 + bt2 ; o = exp(s)*o + t ----------
        gemm_tile(aH, wl + 3 * 16384, acc, lane, wm, wn, rowoff, koff);
        #pragma unroll
        for (int mt = 0; mt < 2; mt++)
            #pragma unroll
            for (int nt = 0; nt < 4; nt++) {
                int col0 = wn * 32 + nt * 8 + tg * 2;
                float2 bb = *reinterpret_cast<const float2*>(bt2 + layer * HALFD + col0);
                int r0 = wm * 32 + mt * 16 + g;
                float2 sa = *reinterpret_cast<float2*>(s_s + r0 * LDO + col0);
                float2 sb = *reinterpret_cast<float2*>(s_s + (r0 + 8) * LDO + col0);
                float2 oa = *reinterpret_cast<float2*>(o_s + r0 * LDO + col0);
                float2 ob = *reinterpret_cast<float2*>(o_s + (r0 + 8) * LDO + col0);
                oa.x = __expf(sa.x) * oa.x + acc[mt][nt][0] + bb.x;
                oa.y = __expf(sa.y) * oa.y + acc[mt][nt][1] + bb.y;
                ob.x = __expf(sb.x) * ob.x + acc[mt][nt][2] + bb.x;
                ob.y = __expf(sb.y) * ob.y + acc[mt][nt][3] + bb.y;
                *reinterpret_cast<float2*>(o_s + r0 * LDO + col0)       = oa;
                *reinterpret_cast<float2*>(o_s + (r0 + 8) * LDO + col0) = ob;
            }
        // next layer's post-GEMM1 sync protects h_s; o_s/s_s are thread-private positions
    }
    __syncthreads();

    // Odd half of output
    for (int idx = tid; idx < MT * 256; idx += THREADS) {
        int r = idx >> 8, c = idx & 255;
        out[(size_t)(row0 + r) * DD + 256 + c] = o_s[r * LDO + c];
    }

    // Deterministic logjac reduction: intra-warp over tg, then across the 8 n-warps.
    #pragma unroll
    for (int k = 0; k < 4; k++) {
        float v = lj[k];
        v += __shfl_down_sync(0xffffffffu, v, 2);
        v += __shfl_down_sync(0xffffffffu, v, 1);
        if (tg == 0) {
            int r = wm * 32 + (k >> 1) * 16 + (k & 1) * 8 + g;
            lj_s[r * 8 + wn] = v;
        }
    }
    __syncthreads();
    if (tid < MT) {
        float v = 0.f;
        #pragma unroll
        for (int j = 0; j < 8; j++) v += lj_s[tid * 8 + j];
        out[(size_t)NROWS * DD + row0 + tid] = v;
    }
}

extern "C" void kernel_launch(void* const* d_in, const int* in_sizes, int n_in,
                              void* d_out, int out_size)
{
    const float* z   = (const float*)d_in[0];
    const float* Ws1 = (const float*)d_in[1];
    const float* bs1 = (const float*)d_in[2];
    const float* Ws2 = (const float*)d_in[3];
    const float* bs2 = (const float*)d_in[4];
    const float* Wt1 = (const float*)d_in[5];
    const float* bt1 = (const float*)d_in[6];
    const float* Wt2 = (const float*)d_in[7];
    const float* bt2 = (const float*)d_in[8];
    float* out = (float*)d_out;

    static bool attr_set = false;
    if (!attr_set) {
        cudaFuncSetAttribute(nvp_main, cudaFuncAttributeMaxDynamicSharedMemorySize, SM_TOT);
        attr_set = true;
    }

    // 1) pack weights to fragment-native fp16 (runs every call; deterministic)
    pack_w<<<(NL * 4 * 16 * 32 * 32 + 255) / 256, 256>>>(Ws1, Ws2, Wt1, Wt2);

    // 2) fused 8-layer RealNVP
    nvp_main<<<NROWS / MT, THREADS, SM_TOT>>>(z, bs1, bs2, bt1, bt2, out);
}